// round 3
// baseline (speedup 1.0000x reference)
#include <cuda_runtime.h>
#include <cstdint>

// Problem constants (fixed by setup_inputs)
constexpr int B_   = 4;
constexpr int M_   = 65536;
constexpr int N_   = 16384;
constexpr int CPRE = 64;
constexpr int CCUR = 128;
constexpr int CIN  = 192;   // CPRE + CCUR
constexpr int DOUT = 128;

constexpr int MT      = 128;   // m-tile per block
constexpr int THREADS = 256;
constexpr int ROWS    = MT + 1; // x_s row stride (odd -> conflict-free STS)

// Scratch: cur_x transposed to (B, N, C) so gathers are contiguous 512B reads.
__device__ float g_curT[(size_t)B_ * N_ * CCUR]; // 32 MiB

// ---------------------------------------------------------------------------
// Kernel 1: transpose cur_x (B,C,N) -> g_curT (B,N,C)
// ---------------------------------------------------------------------------
__global__ void transpose_kernel(const float* __restrict__ cur) {
    __shared__ float t[32][33];
    int b  = blockIdx.z;
    int c0 = blockIdx.y * 32;
    int n0 = blockIdx.x * 32;
    const float* src = cur + (size_t)b * CCUR * N_;
    #pragma unroll
    for (int r = threadIdx.y; r < 32; r += 8)
        t[r][threadIdx.x] = src[(size_t)(c0 + r) * N_ + n0 + threadIdx.x];
    __syncthreads();
    float* dst = g_curT + (size_t)b * N_ * CCUR;
    #pragma unroll
    for (int r = threadIdx.y; r < 32; r += 8)
        dst[(size_t)(n0 + r) * CCUR + c0 + threadIdx.x] = t[threadIdx.x][r];
}

// ---------------------------------------------------------------------------
// f32x2 packed-FMA helpers (FFMA2 only reachable via PTX fma.rn.f32x2)
// ---------------------------------------------------------------------------
__device__ __forceinline__ unsigned long long pack2(float lo, float hi) {
    unsigned long long r;
    asm("mov.b64 %0, {%1, %2};" : "=l"(r) : "f"(lo), "f"(hi));
    return r;
}
__device__ __forceinline__ void fma2(unsigned long long& acc,
                                     unsigned long long a, unsigned long long b) {
    asm("fma.rn.f32x2 %0, %1, %2, %0;" : "+l"(acc) : "l"(a), "l"(b));
}
__device__ __forceinline__ float2 unpack2(unsigned long long v) {
    float2 r;
    asm("mov.b64 {%0, %1}, %2;" : "=f"(r.x), "=f"(r.y) : "l"(v));
    return r;
}

// ---------------------------------------------------------------------------
// Kernel 2: fused gather + concat + GEMM(192x128) + BN + ReLU + transpose-out
// Block: 256 threads, 128 m-columns of one batch, all 128 outputs.
// Thread microtile: 8 m x 8 d. d-mapping: thread dt owns pairs
//   d = 2*dt + 32*q + {0,1}, q = 0..3  -> conflict-free LDS.64 on w_s.
// ---------------------------------------------------------------------------
extern __shared__ float smem[];

__global__ __launch_bounds__(THREADS, 1)
void fused_kernel(const float* __restrict__ pre_x,
                  const int* __restrict__ up_idx,
                  const float* __restrict__ w,
                  const float* __restrict__ bias,
                  const float* __restrict__ gamma,
                  const float* __restrict__ beta,
                  const float* __restrict__ rmean,
                  const float* __restrict__ rvar,
                  float* __restrict__ out) {
    const int b   = blockIdx.y;
    const int m0  = blockIdx.x * MT;
    const int tid = threadIdx.x;

    int*   idx_s = (int*)smem;                 // 128 ints
    float* w_s   = smem + 128;                 // [192][128]
    float* x_s   = w_s + CIN * DOUT;           // [192][129]  (k-major, row stride 129)

    // ---- stage idx (int32 input; mask defends against any bad values) ----
    if (tid < MT) idx_s[tid] = up_idx[(size_t)b * M_ + m0 + tid] & (N_ - 1);

    // ---- stage w (row-major copy, float4) ----
    {
        const float4* w4  = (const float4*)w;
        float4*       ws4 = (float4*)w_s;
        for (int i = tid; i < CIN * DOUT / 4; i += THREADS)
            ws4[i] = w4[i];
    }

    // ---- stage pre_x part of x: rows 0..63 ----
    {
        const float* src = pre_x + (size_t)b * CPRE * M_ + m0;
        for (int i = tid; i < CPRE * MT; i += THREADS) {
            int c  = i >> 7;       // /128
            int ml = i & 127;
            x_s[c * ROWS + ml] = src[(size_t)c * M_ + ml];   // coalesced LDG, conflict-free STS
        }
    }
    __syncthreads();   // idx_s visible

    // ---- stage gathered feat part of x: rows 64..191 ----
    {
        const float* base = g_curT + (size_t)b * N_ * CCUR;
        for (int i = tid; i < MT * CCUR; i += THREADS) {
            int ml = i >> 7;       // m within tile (warp-uniform)
            int c  = i & 127;      // channel (contiguous across warp -> 128B LDG)
            x_s[(CPRE + c) * ROWS + ml] = base[(size_t)idx_s[ml] * CCUR + c];
        }
    }
    __syncthreads();

    // ---- register-tiled GEMM ----
    const int mt = tid >> 4;   // 0..15  -> 8 consecutive m each
    const int dt = tid & 15;   // 0..15  -> d pairs 2*dt + 32*q
    const float* xp = x_s + mt * 8;
    const float* wp = w_s + dt * 2;

    unsigned long long acc[8][4];
    #pragma unroll
    for (int j = 0; j < 8; j++)
        #pragma unroll
        for (int q = 0; q < 4; q++) acc[j][q] = 0ULL;

    #pragma unroll 2
    for (int k = 0; k < CIN; k++) {
        unsigned long long wv[4];
        const float* wrow = wp + (size_t)k * DOUT;
        #pragma unroll
        for (int q = 0; q < 4; q++) {
            float2 t = *(const float2*)(wrow + 32 * q);   // LDS.64, banks 2dt,2dt+1
            wv[q] = pack2(t.x, t.y);
        }
        #pragma unroll
        for (int j = 0; j < 8; j++) {
            float xv = xp[(size_t)k * ROWS + j]; // broadcast within half-warp
            unsigned long long x2 = pack2(xv, xv);
            #pragma unroll
            for (int q = 0; q < 4; q++) fma2(acc[j][q], x2, wv[q]);
        }
    }

    // ---- folded BN (inference) + ReLU epilogue ----
    float sc[8], bi[8];
    #pragma unroll
    for (int q = 0; q < 4; q++) {
        #pragma unroll
        for (int r = 0; r < 2; r++) {
            int d = 2 * dt + 32 * q + r;
            float s = gamma[d] * rsqrtf(rvar[d] + 1e-5f);
            sc[2 * q + r] = s;
            bi[2 * q + r] = (bias[d] - rmean[d]) * s + beta[d];
        }
    }

    float* obase = out + ((size_t)b * M_ + m0 + mt * 8) * DOUT + 2 * dt;
    #pragma unroll
    for (int j = 0; j < 8; j++) {
        float* orow = obase + (size_t)j * DOUT;
        #pragma unroll
        for (int q = 0; q < 4; q++) {
            float2 r = unpack2(acc[j][q]);
            float v0 = fmaxf(fmaf(r.x, sc[2 * q],     bi[2 * q]),     0.0f);
            float v1 = fmaxf(fmaf(r.y, sc[2 * q + 1], bi[2 * q + 1]), 0.0f);
            *(float2*)(orow + 32 * q) = make_float2(v0, v1);   // STG.64, coalesced 128B segs
        }
    }
}

// ---------------------------------------------------------------------------
extern "C" void kernel_launch(void* const* d_in, const int* in_sizes, int n_in,
                              void* d_out, int out_size) {
    const float* pre_x  = (const float*)d_in[0];
    const float* cur_x  = (const float*)d_in[1];
    const int*   up_idx = (const int*)d_in[2];     // int32 (JAX x64 disabled)
    const float* w      = (const float*)d_in[3];
    const float* bias   = (const float*)d_in[4];
    const float* gamma  = (const float*)d_in[5];
    const float* beta   = (const float*)d_in[6];
    const float* rmean  = (const float*)d_in[7];
    const float* rvar   = (const float*)d_in[8];
    float*       out    = (float*)d_out;

    // 1) transpose cur_x into scratch (contiguous gather columns)
    dim3 tg(N_ / 32, CCUR / 32, B_);
    transpose_kernel<<<tg, dim3(32, 8)>>>(cur_x);

    // 2) fused main kernel
    size_t smem_bytes = (size_t)(128 + CIN * DOUT + CIN * ROWS) * sizeof(float); // ~193 KB
    cudaFuncSetAttribute(fused_kernel, cudaFuncAttributeMaxDynamicSharedMemorySize,
                         (int)smem_bytes);
    dim3 grid(M_ / MT, B_);
    fused_kernel<<<grid, THREADS, smem_bytes>>>(pre_x, up_idx, w, bias, gamma,
                                                beta, rmean, rvar, out);
}

// round 6
// speedup vs baseline: 1.7663x; 1.7663x over previous
#include <cuda_runtime.h>
#include <cuda_bf16.h>
#include <cstdint>

// Problem constants
constexpr int B_   = 4;
constexpr int M_   = 65536;
constexpr int N_   = 16384;
constexpr int CPRE = 64;
constexpr int CCUR = 128;
constexpr int CIN  = 192;
constexpr int DOUT = 128;

constexpr int MT      = 128;
constexpr int THREADS = 256;

// SMEM layouts (bf16 element strides; all rows 16B aligned, word stride ≡ 4 mod 8
// -> ldmatrix 8-row phases tile all 32 banks)
constexpr int SXA = 136;   // pre_x tile, k-major: [64 k][128 m + pad]
constexpr int SXG = 136;   // gather tile, m-major: [128 m][128 k' + pad]
constexpr int SW  = 200;   // w tile, d-major: [128 d][192 k + pad]

constexpr int SM_IDX = 0;                       // 128 int
constexpr int SM_SC  = 512;                     // 128 f
constexpr int SM_BI  = 1024;                    // 128 f
constexpr int SM_XAH = 2048;                    // 64*136*2  = 17408
constexpr int SM_XAL = SM_XAH + 64 * SXA * 2;   // 19456
constexpr int SM_XGH = SM_XAL + 64 * SXA * 2;   // 36864, 128*136*2 = 34816
constexpr int SM_XGL = SM_XGH + 128 * SXG * 2;  // 71680
constexpr int SM_WH  = SM_XGL + 128 * SXG * 2;  // 106496, 128*200*2 = 51200
constexpr int SM_WL  = SM_WH + 128 * SW * 2;    // 157696
constexpr int SM_TOT = SM_WL + 128 * SW * 2;    // 208896 (~204 KB)

// Scratch
__device__ float    g_curT[(size_t)B_ * N_ * CCUR];  // 32 MiB, (B,N,C)
__device__ uint32_t g_wh[128 * (SW / 2)];            // W hi, smem image [d][k/2]
__device__ uint32_t g_wl[128 * (SW / 2)];            // W lo

// ---------------------------------------------------------------------------
__global__ void transpose_kernel(const float* __restrict__ cur) {
    __shared__ float t[32][33];
    int b  = blockIdx.z;
    int c0 = blockIdx.y * 32;
    int n0 = blockIdx.x * 32;
    const float* src = cur + (size_t)b * CCUR * N_;
    #pragma unroll
    for (int r = threadIdx.y; r < 32; r += 8)
        t[r][threadIdx.x] = src[(size_t)(c0 + r) * N_ + n0 + threadIdx.x];
    __syncthreads();
    float* dst = g_curT + (size_t)b * N_ * CCUR;
    #pragma unroll
    for (int r = threadIdx.y; r < 32; r += 8)
        dst[(size_t)(n0 + r) * CCUR + c0 + threadIdx.x] = t[threadIdx.x][r];
}

__device__ __forceinline__ uint32_t pk2(float a, float b) {
    __nv_bfloat162 t = __floats2bfloat162_rn(a, b);
    return *(uint32_t*)&t;
}
__device__ __forceinline__ void split2(float a, float b, uint32_t& hi, uint32_t& lo) {
    float ah = __bfloat162float(__float2bfloat16_rn(a));
    float bh = __bfloat162float(__float2bfloat16_rn(b));
    hi = pk2(ah, bh);
    lo = pk2(a - ah, b - bh);
}

// Pre-split W into its smem image: [d][k] rows, hi/lo bf16 pairs
__global__ void wsplit_kernel(const float* __restrict__ w) {
    int i = blockIdx.x * 256 + threadIdx.x;   // 128 d x 96 k-pairs
    if (i >= DOUT * (CIN / 2)) return;
    int d = i & 127, kp = i >> 7;
    float a = w[(size_t)(2 * kp) * DOUT + d];
    float c = w[(size_t)(2 * kp + 1) * DOUT + d];
    uint32_t hi, lo;
    split2(a, c, hi, lo);
    g_wh[d * (SW / 2) + kp] = hi;
    g_wl[d * (SW / 2) + kp] = lo;
}

// ---------------------------------------------------------------------------
__device__ __forceinline__ uint32_t smem_u32(const void* p) {
    uint32_t a;
    asm("{ .reg .u64 t; cvta.to.shared.u64 t, %1; cvt.u32.u64 %0, t; }" : "=r"(a) : "l"(p));
    return a;
}

#define LDSM4(r0, r1, r2, r3, addr)                                          \
    asm volatile("ldmatrix.sync.aligned.m8n8.x4.shared.b16 {%0,%1,%2,%3}, [%4];" \
                 : "=r"(r0), "=r"(r1), "=r"(r2), "=r"(r3) : "r"(addr))
#define LDSM4T(r0, r1, r2, r3, addr)                                         \
    asm volatile("ldmatrix.sync.aligned.m8n8.x4.trans.shared.b16 {%0,%1,%2,%3}, [%4];" \
                 : "=r"(r0), "=r"(r1), "=r"(r2), "=r"(r3) : "r"(addr))
#define MMA16816(c, a, b)                                                    \
    asm volatile("mma.sync.aligned.m16n8k16.row.col.f32.bf16.bf16.f32 "       \
                 "{%0,%1,%2,%3}, {%4,%5,%6,%7}, {%8,%9}, {%0,%1,%2,%3};"      \
                 : "+f"((c)[0]), "+f"((c)[1]), "+f"((c)[2]), "+f"((c)[3])     \
                 : "r"((a)[0]), "r"((a)[1]), "r"((a)[2]), "r"((a)[3]),        \
                   "r"((b)[0]), "r"((b)[1]))

extern __shared__ char smc[];

__global__ __launch_bounds__(THREADS, 1)
void fused_kernel(const float* __restrict__ pre_x,
                  const int* __restrict__ up_idx,
                  const float* __restrict__ bias,
                  const float* __restrict__ gamma,
                  const float* __restrict__ beta,
                  const float* __restrict__ rmean,
                  const float* __restrict__ rvar,
                  float* __restrict__ out) {
    const int b    = blockIdx.y;
    const int m0   = blockIdx.x * MT;
    const int tid  = threadIdx.x;
    const int wid  = tid >> 5;
    const int lane = tid & 31;

    int*   idx_s = (int*)(smc + SM_IDX);
    float* sc_s  = (float*)(smc + SM_SC);
    float* bi_s  = (float*)(smc + SM_BI);

    if (tid < MT) {
        idx_s[tid] = up_idx[(size_t)b * M_ + m0 + tid] & (N_ - 1);
        float s = gamma[tid] * rsqrtf(rvar[tid] + 1e-5f);
        sc_s[tid] = s;
        bi_s[tid] = (bias[tid] - rmean[tid]) * s + beta[tid];
    }

    // ---- stage W tiles: straight uint4 copy of precomputed smem image ----
    {
        const uint4* sh = (const uint4*)g_wh;
        const uint4* sl = (const uint4*)g_wl;
        uint4* dh = (uint4*)(smc + SM_WH);
        uint4* dl = (uint4*)(smc + SM_WL);
        for (int i = tid; i < 128 * SW * 2 / 16; i += THREADS) {
            dh[i] = sh[i];
            dl[i] = sl[i];
        }
    }

    // ---- stage pre_x -> XA (k-major). lane-consecutive m: coalesced LDG,
    //      consecutive STS words (conflict-free) ----
    {
        const float* base = pre_x + (size_t)b * CPRE * M_ + m0;
        uint32_t* xah = (uint32_t*)(smc + SM_XAH);
        uint32_t* xal = (uint32_t*)(smc + SM_XAL);
        for (int i = tid; i < CPRE * 64; i += THREADS) {
            int k = i >> 6, mp = i & 63;
            float2 v = *(const float2*)(base + (size_t)k * M_ + 2 * mp);
            uint32_t hi, lo;
            split2(v.x, v.y, hi, lo);
            xah[k * (SXA / 2) + mp] = hi;
            xal[k * (SXA / 2) + mp] = lo;
        }
    }
    __syncthreads();   // idx_s visible

    // ---- stage gather -> XG (m-major). warp reads one 512B row; STS.64
    //      lane-consecutive -> conflict-free ----
    {
        const float* base = g_curT + (size_t)b * N_ * CCUR;
        for (int i = tid; i < MT * 32; i += THREADS) {
            int m = i >> 5, c4 = i & 31;
            float4 v = *(const float4*)(base + (size_t)idx_s[m] * CCUR + 4 * c4);
            uint32_t h0, l0, h1, l1;
            split2(v.x, v.y, h0, l0);
            split2(v.z, v.w, h1, l1);
            *(uint2*)(smc + SM_XGH + (m * SXG + 4 * c4) * 2) = make_uint2(h0, h1);
            *(uint2*)(smc + SM_XGL + (m * SXG + 4 * c4) * 2) = make_uint2(l0, l1);
        }
    }
    __syncthreads();

    // ---- mainloop ----
    const int wm = wid & 1;    // m-half (64)
    const int wd = wid >> 1;   // d-quarter (32)
    const int r  = lane & 7;
    const int q  = lane >> 3;

    // per-lane ldmatrix base offsets (bytes)
    const uint32_t base_u32 = smem_u32(smc);
    // pre tile (trans): rows k, cols m
    const int krA  = r + ((q >= 2) ? 8 : 0);
    const int mcA  = wm * 64 + ((q & 1) ? 8 : 0);
    uint32_t aP_h = base_u32 + SM_XAH + (krA * SXA + mcA) * 2;
    uint32_t aP_l = base_u32 + SM_XAL + (krA * SXA + mcA) * 2;
    // gather tile (non-trans): rows m, cols k'
    const int mrA  = wm * 64 + r + ((q & 1) ? 8 : 0);
    const int kcA  = (q >= 2) ? 8 : 0;
    uint32_t aG_h = base_u32 + SM_XGH + (mrA * SXG + kcA) * 2;
    uint32_t aG_l = base_u32 + SM_XGL + (mrA * SXG + kcA) * 2;
    // w tile (non-trans): rows d, cols k
    const int drB  = wd * 32 + r + ((q >= 2) ? 8 : 0);
    const int kcB  = (q & 1) ? 8 : 0;
    uint32_t bW_h = base_u32 + SM_WH + (drB * SW + kcB) * 2;
    uint32_t bW_l = base_u32 + SM_WL + (drB * SW + kcB) * 2;

    float acc[4][4][4];
    #pragma unroll
    for (int i = 0; i < 4; i++)
        #pragma unroll
        for (int j = 0; j < 4; j++)
            #pragma unroll
            for (int e = 0; e < 4; e++) acc[i][j][e] = 0.0f;

    uint32_t ah[4][4], al[4][4], bh[4][2], bl[4][2];

    // ksteps 0..3: pre_x region (k-major, trans LDSM)
    #pragma unroll 2
    for (int ks = 0; ks < 4; ks++) {
        const int k0 = ks * 16;
        #pragma unroll
        for (int mf = 0; mf < 4; mf++) {
            uint32_t o = (uint32_t)(k0 * SXA + mf * 16) * 2;
            LDSM4T(ah[mf][0], ah[mf][1], ah[mf][2], ah[mf][3], aP_h + o);
            LDSM4T(al[mf][0], al[mf][1], al[mf][2], al[mf][3], aP_l + o);
        }
        #pragma unroll
        for (int g = 0; g < 2; g++) {
            uint32_t o = (uint32_t)(g * 16 * SW + k0) * 2;
            LDSM4(bh[2*g][0], bh[2*g][1], bh[2*g+1][0], bh[2*g+1][1], bW_h + o);
            LDSM4(bl[2*g][0], bl[2*g][1], bl[2*g+1][0], bl[2*g+1][1], bW_l + o);
        }
        #pragma unroll
        for (int mf = 0; mf < 4; mf++)
            #pragma unroll
            for (int nf = 0; nf < 4; nf++) {
                MMA16816(acc[mf][nf], ah[mf], bh[nf]);
                MMA16816(acc[mf][nf], ah[mf], bl[nf]);
                MMA16816(acc[mf][nf], al[mf], bh[nf]);
            }
    }

    // ksteps 4..11: gather region (m-major, non-trans LDSM)
    #pragma unroll 2
    for (int ks = 4; ks < 12; ks++) {
        const int k0  = ks * 16;
        const int kp0 = k0 - 64;
        #pragma unroll
        for (int mf = 0; mf < 4; mf++) {
            uint32_t o = (uint32_t)(mf * 16 * SXG + kp0) * 2;
            LDSM4(ah[mf][0], ah[mf][1], ah[mf][2], ah[mf][3], aG_h + o);
            LDSM4(al[mf][0], al[mf][1], al[mf][2], al[mf][3], aG_l + o);
        }
        #pragma unroll
        for (int g = 0; g < 2; g++) {
            uint32_t o = (uint32_t)(g * 16 * SW + k0) * 2;
            LDSM4(bh[2*g][0], bh[2*g][1], bh[2*g+1][0], bh[2*g+1][1], bW_h + o);
            LDSM4(bl[2*g][0], bl[2*g][1], bl[2*g+1][0], bl[2*g+1][1], bW_l + o);
        }
        #pragma unroll
        for (int mf = 0; mf < 4; mf++)
            #pragma unroll
            for (int nf = 0; nf < 4; nf++) {
                MMA16816(acc[mf][nf], ah[mf], bh[nf]);
                MMA16816(acc[mf][nf], ah[mf], bl[nf]);
                MMA16816(acc[mf][nf], al[mf], bh[nf]);
            }
    }

    // ---- epilogue: BN + ReLU + STG.64 ----
    const int gid = lane >> 2;
    const int tig = lane & 3;
    const size_t obase = ((size_t)b * M_ + m0) * DOUT;

    #pragma unroll
    for (int nf = 0; nf < 4; nf++) {
        int d0 = wd * 32 + nf * 8 + 2 * tig;
        float s0 = sc_s[d0], s1 = sc_s[d0 + 1];
        float b0 = bi_s[d0], b1 = bi_s[d0 + 1];
        #pragma unroll
        for (int mf = 0; mf < 4; mf++) {
            int row0 = m0 == 0 ? 0 : 0;  // (placate compiler ordering)
            int rA = wm * 64 + mf * 16 + gid;
            int rB = rA + 8;
            float2 v0, v1;
            v0.x = fmaxf(fmaf(acc[mf][nf][0], s0, b0), 0.0f);
            v0.y = fmaxf(fmaf(acc[mf][nf][1], s1, b1), 0.0f);
            v1.x = fmaxf(fmaf(acc[mf][nf][2], s0, b0), 0.0f);
            v1.y = fmaxf(fmaf(acc[mf][nf][3], s1, b1), 0.0f);
            *(float2*)(out + obase + (size_t)rA * DOUT + d0) = v0;
            *(float2*)(out + obase + (size_t)rB * DOUT + d0) = v1;
            (void)row0;
        }
    }
}

// ---------------------------------------------------------------------------
extern "C" void kernel_launch(void* const* d_in, const int* in_sizes, int n_in,
                              void* d_out, int out_size) {
    const float* pre_x  = (const float*)d_in[0];
    const float* cur_x  = (const float*)d_in[1];
    const int*   up_idx = (const int*)d_in[2];
    const float* w      = (const float*)d_in[3];
    const float* bias   = (const float*)d_in[4];
    const float* gamma  = (const float*)d_in[5];
    const float* beta   = (const float*)d_in[6];
    const float* rmean  = (const float*)d_in[7];
    const float* rvar   = (const float*)d_in[8];
    float*       out    = (float*)d_out;

    dim3 tg(N_ / 32, CCUR / 32, B_);
    transpose_kernel<<<tg, dim3(32, 8)>>>(cur_x);
    wsplit_kernel<<<48, 256>>>(w);

    cudaFuncSetAttribute(fused_kernel, cudaFuncAttributeMaxDynamicSharedMemorySize, SM_TOT);
    dim3 grid(M_ / MT, B_);
    fused_kernel<<<grid, THREADS, SM_TOT>>>(pre_x, up_idx, bias, gamma,
                                            beta, rmean, rvar, out);
}

// round 7
// speedup vs baseline: 1.9508x; 1.1045x over previous
#include <cuda_runtime.h>
#include <cuda_bf16.h>
#include <cstdint>

// Problem constants
constexpr int B_   = 4;
constexpr int M_   = 65536;
constexpr int N_   = 16384;
constexpr int CPRE = 64;
constexpr int CCUR = 128;
constexpr int CIN  = 192;
constexpr int DOUT = 128;

constexpr int MT      = 128;
constexpr int THREADS = 512;   // 16 warps -> 4 per SMSP

// SMEM layouts (bf16 element strides; word stride ≡ 4 mod 8 -> conflict-free LDSM)
constexpr int SXA = 136;   // pre_x tile, k-major: [64 k][128 m + pad]
constexpr int SXG = 136;   // gather tile, m-major: [128 m][128 k' + pad]
constexpr int SW  = 200;   // w tile, d-major: [128 d][192 k + pad]

constexpr int SM_IDX = 0;                       // 128 int
constexpr int SM_SC  = 512;                     // 128 f
constexpr int SM_BI  = 1024;                    // 128 f
constexpr int SM_XAH = 2048;
constexpr int SM_XAL = SM_XAH + 64 * SXA * 2;
constexpr int SM_XGH = SM_XAL + 64 * SXA * 2;
constexpr int SM_XGL = SM_XGH + 128 * SXG * 2;
constexpr int SM_WH  = SM_XGL + 128 * SXG * 2;
constexpr int SM_WL  = SM_WH + 128 * SW * 2;
constexpr int SM_TOT = SM_WL + 128 * SW * 2;    // 208896 (~204 KB)

// Scratch
__device__ float    g_curT[(size_t)B_ * N_ * CCUR];  // 32 MiB, (B,N,C)
__device__ uint32_t g_wh[128 * (SW / 2)];            // W hi, smem image [d][k/2]
__device__ uint32_t g_wl[128 * (SW / 2)];            // W lo

// ---------------------------------------------------------------------------
__global__ void transpose_kernel(const float* __restrict__ cur) {
    __shared__ float t[32][33];
    int b  = blockIdx.z;
    int c0 = blockIdx.y * 32;
    int n0 = blockIdx.x * 32;
    const float* src = cur + (size_t)b * CCUR * N_;
    #pragma unroll
    for (int r = threadIdx.y; r < 32; r += 8)
        t[r][threadIdx.x] = src[(size_t)(c0 + r) * N_ + n0 + threadIdx.x];
    __syncthreads();
    float* dst = g_curT + (size_t)b * N_ * CCUR;
    #pragma unroll
    for (int r = threadIdx.y; r < 32; r += 8)
        dst[(size_t)(n0 + r) * CCUR + c0 + threadIdx.x] = t[threadIdx.x][r];
}

__device__ __forceinline__ uint32_t pk2(float a, float b) {
    __nv_bfloat162 t = __floats2bfloat162_rn(a, b);
    return *(uint32_t*)&t;
}
__device__ __forceinline__ void split2(float a, float b, uint32_t& hi, uint32_t& lo) {
    float ah = __bfloat162float(__float2bfloat16_rn(a));
    float bh = __bfloat162float(__float2bfloat16_rn(b));
    hi = pk2(ah, bh);
    lo = pk2(a - ah, b - bh);
}

// Pre-split W into its smem image: [d][k] rows, hi/lo bf16 pairs
__global__ void wsplit_kernel(const float* __restrict__ w) {
    int i = blockIdx.x * 256 + threadIdx.x;   // 128 d x 96 k-pairs
    if (i >= DOUT * (CIN / 2)) return;
    int d = i & 127, kp = i >> 7;
    float a = w[(size_t)(2 * kp) * DOUT + d];
    float c = w[(size_t)(2 * kp + 1) * DOUT + d];
    uint32_t hi, lo;
    split2(a, c, hi, lo);
    g_wh[d * (SW / 2) + kp] = hi;
    g_wl[d * (SW / 2) + kp] = lo;
}

// ---------------------------------------------------------------------------
__device__ __forceinline__ uint32_t smem_u32(const void* p) {
    uint32_t a;
    asm("{ .reg .u64 t; cvta.to.shared.u64 t, %1; cvt.u32.u64 %0, t; }" : "=r"(a) : "l"(p));
    return a;
}
__device__ __forceinline__ void cp_async16(uint32_t dst, const void* src) {
    asm volatile("cp.async.cg.shared.global [%0], [%1], 16;" :: "r"(dst), "l"(src));
}

#define LDSM4(r0, r1, r2, r3, addr)                                          \
    asm volatile("ldmatrix.sync.aligned.m8n8.x4.shared.b16 {%0,%1,%2,%3}, [%4];" \
                 : "=r"(r0), "=r"(r1), "=r"(r2), "=r"(r3) : "r"(addr))
#define LDSM4T(r0, r1, r2, r3, addr)                                         \
    asm volatile("ldmatrix.sync.aligned.m8n8.x4.trans.shared.b16 {%0,%1,%2,%3}, [%4];" \
                 : "=r"(r0), "=r"(r1), "=r"(r2), "=r"(r3) : "r"(addr))
#define MMA16816(c, a, b)                                                    \
    asm volatile("mma.sync.aligned.m16n8k16.row.col.f32.bf16.bf16.f32 "       \
                 "{%0,%1,%2,%3}, {%4,%5,%6,%7}, {%8,%9}, {%0,%1,%2,%3};"      \
                 : "+f"((c)[0]), "+f"((c)[1]), "+f"((c)[2]), "+f"((c)[3])     \
                 : "r"((a)[0]), "r"((a)[1]), "r"((a)[2]), "r"((a)[3]),        \
                   "r"((b)[0]), "r"((b)[1]))

extern __shared__ char smc[];

__global__ __launch_bounds__(THREADS, 1)
void fused_kernel(const float* __restrict__ pre_x,
                  const int* __restrict__ up_idx,
                  const float* __restrict__ bias,
                  const float* __restrict__ gamma,
                  const float* __restrict__ beta,
                  const float* __restrict__ rmean,
                  const float* __restrict__ rvar,
                  float* __restrict__ out) {
    const int b    = blockIdx.y;
    const int m0   = blockIdx.x * MT;
    const int tid  = threadIdx.x;
    const int wid  = tid >> 5;
    const int lane = tid & 31;

    int*   idx_s = (int*)(smc + SM_IDX);
    float* sc_s  = (float*)(smc + SM_SC);
    float* bi_s  = (float*)(smc + SM_BI);
    const uint32_t base_u32 = smem_u32(smc);

    if (tid < MT) {
        idx_s[tid] = up_idx[(size_t)b * M_ + m0 + tid] & (N_ - 1);
        float s = gamma[tid] * rsqrtf(rvar[tid] + 1e-5f);
        sc_s[tid] = s;
        bi_s[tid] = (bias[tid] - rmean[tid]) * s + beta[tid];
    }

    // ---- stage W tiles via cp.async (no register round-trip) ----
    {
        const char* sh = (const char*)g_wh;
        const char* sl = (const char*)g_wl;
        for (int i = tid; i < 128 * SW * 2 / 16; i += THREADS) {
            cp_async16(base_u32 + SM_WH + 16 * i, sh + 16 * i);
            cp_async16(base_u32 + SM_WL + 16 * i, sl + 16 * i);
        }
        asm volatile("cp.async.commit_group;");
    }

    // ---- stage pre_x -> XA (k-major) ----
    {
        const float* base = pre_x + (size_t)b * CPRE * M_ + m0;
        uint32_t* xah = (uint32_t*)(smc + SM_XAH);
        uint32_t* xal = (uint32_t*)(smc + SM_XAL);
        for (int i = tid; i < CPRE * 64; i += THREADS) {
            int k = i >> 6, mp = i & 63;
            float2 v = *(const float2*)(base + (size_t)k * M_ + 2 * mp);
            uint32_t hi, lo;
            split2(v.x, v.y, hi, lo);
            xah[k * (SXA / 2) + mp] = hi;
            xal[k * (SXA / 2) + mp] = lo;
        }
    }
    __syncthreads();   // idx_s visible

    // ---- stage gather -> XG (m-major) ----
    {
        const float* base = g_curT + (size_t)b * N_ * CCUR;
        for (int i = tid; i < MT * 32; i += THREADS) {
            int m = i >> 5, c4 = i & 31;
            float4 v = *(const float4*)(base + (size_t)idx_s[m] * CCUR + 4 * c4);
            uint32_t h0, l0, h1, l1;
            split2(v.x, v.y, h0, l0);
            split2(v.z, v.w, h1, l1);
            *(uint2*)(smc + SM_XGH + (m * SXG + 4 * c4) * 2) = make_uint2(h0, h1);
            *(uint2*)(smc + SM_XGL + (m * SXG + 4 * c4) * 2) = make_uint2(l0, l1);
        }
    }
    asm volatile("cp.async.wait_group 0;" ::: "memory");
    __syncthreads();

    // ---- mainloop: warp tile 32m x 32d ----
    const int wm = wid & 3;    // m-quarter (32)
    const int wd = wid >> 2;   // d-quarter (32)
    const int r  = lane & 7;
    const int q  = lane >> 3;

    // pre tile (trans): rows k, cols m
    const int krA = r + ((q >= 2) ? 8 : 0);
    const int mcA = wm * 32 + ((q & 1) ? 8 : 0);
    uint32_t aP_h = base_u32 + SM_XAH + (krA * SXA + mcA) * 2;
    uint32_t aP_l = base_u32 + SM_XAL + (krA * SXA + mcA) * 2;
    // gather tile (non-trans): rows m, cols k'
    const int mrA = wm * 32 + r + ((q & 1) ? 8 : 0);
    const int kcA = (q >= 2) ? 8 : 0;
    uint32_t aG_h = base_u32 + SM_XGH + (mrA * SXG + kcA) * 2;
    uint32_t aG_l = base_u32 + SM_XGL + (mrA * SXG + kcA) * 2;
    // w tile (non-trans): rows d, cols k
    const int drB = wd * 32 + r + ((q >= 2) ? 8 : 0);
    const int kcB = (q & 1) ? 8 : 0;
    uint32_t bW_h = base_u32 + SM_WH + (drB * SW + kcB) * 2;
    uint32_t bW_l = base_u32 + SM_WL + (drB * SW + kcB) * 2;

    float acc[2][4][4];
    #pragma unroll
    for (int i = 0; i < 2; i++)
        #pragma unroll
        for (int j = 0; j < 4; j++)
            #pragma unroll
            for (int e = 0; e < 4; e++) acc[i][j][e] = 0.0f;

    uint32_t ah[2][4], al[2][4], bh[4][2], bl[4][2];

    // ksteps 0..3: pre_x region (k-major, trans LDSM)
    #pragma unroll
    for (int ks = 0; ks < 4; ks++) {
        const int k0 = ks * 16;
        #pragma unroll
        for (int mf = 0; mf < 2; mf++) {
            uint32_t o = (uint32_t)(k0 * SXA + mf * 16) * 2;
            LDSM4T(ah[mf][0], ah[mf][1], ah[mf][2], ah[mf][3], aP_h + o);
            LDSM4T(al[mf][0], al[mf][1], al[mf][2], al[mf][3], aP_l + o);
        }
        #pragma unroll
        for (int g = 0; g < 2; g++) {
            uint32_t o = (uint32_t)(g * 16 * SW + k0) * 2;
            LDSM4(bh[2*g][0], bh[2*g][1], bh[2*g+1][0], bh[2*g+1][1], bW_h + o);
            LDSM4(bl[2*g][0], bl[2*g][1], bl[2*g+1][0], bl[2*g+1][1], bW_l + o);
        }
        // pass-separated: same-acc reuse distance = 8 independent MMAs
        #pragma unroll
        for (int mf = 0; mf < 2; mf++)
            #pragma unroll
            for (int nf = 0; nf < 4; nf++) MMA16816(acc[mf][nf], ah[mf], bh[nf]);
        #pragma unroll
        for (int mf = 0; mf < 2; mf++)
            #pragma unroll
            for (int nf = 0; nf < 4; nf++) MMA16816(acc[mf][nf], ah[mf], bl[nf]);
        #pragma unroll
        for (int mf = 0; mf < 2; mf++)
            #pragma unroll
            for (int nf = 0; nf < 4; nf++) MMA16816(acc[mf][nf], al[mf], bh[nf]);
    }

    // ksteps 4..11: gather region (m-major, non-trans LDSM)
    #pragma unroll
    for (int ks = 4; ks < 12; ks++) {
        const int k0  = ks * 16;
        const int kp0 = k0 - 64;
        #pragma unroll
        for (int mf = 0; mf < 2; mf++) {
            uint32_t o = (uint32_t)(mf * 16 * SXG + kp0) * 2;
            LDSM4(ah[mf][0], ah[mf][1], ah[mf][2], ah[mf][3], aG_h + o);
            LDSM4(al[mf][0], al[mf][1], al[mf][2], al[mf][3], aG_l + o);
        }
        #pragma unroll
        for (int g = 0; g < 2; g++) {
            uint32_t o = (uint32_t)(g * 16 * SW + k0) * 2;
            LDSM4(bh[2*g][0], bh[2*g][1], bh[2*g+1][0], bh[2*g+1][1], bW_h + o);
            LDSM4(bl[2*g][0], bl[2*g][1], bl[2*g+1][0], bl[2*g+1][1], bW_l + o);
        }
        #pragma unroll
        for (int mf = 0; mf < 2; mf++)
            #pragma unroll
            for (int nf = 0; nf < 4; nf++) MMA16816(acc[mf][nf], ah[mf], bh[nf]);
        #pragma unroll
        for (int mf = 0; mf < 2; mf++)
            #pragma unroll
            for (int nf = 0; nf < 4; nf++) MMA16816(acc[mf][nf], ah[mf], bl[nf]);
        #pragma unroll
        for (int mf = 0; mf < 2; mf++)
            #pragma unroll
            for (int nf = 0; nf < 4; nf++) MMA16816(acc[mf][nf], al[mf], bh[nf]);
    }

    // ---- epilogue: BN + ReLU + STG.64 ----
    const int gid = lane >> 2;
    const int tig = lane & 3;
    const size_t obase = ((size_t)b * M_ + m0) * DOUT;

    #pragma unroll
    for (int nf = 0; nf < 4; nf++) {
        int d0 = wd * 32 + nf * 8 + 2 * tig;
        float s0 = sc_s[d0], s1 = sc_s[d0 + 1];
        float b0 = bi_s[d0], b1 = bi_s[d0 + 1];
        #pragma unroll
        for (int mf = 0; mf < 2; mf++) {
            int rA = wm * 32 + mf * 16 + gid;
            int rB = rA + 8;
            float2 v0, v1;
            v0.x = fmaxf(fmaf(acc[mf][nf][0], s0, b0), 0.0f);
            v0.y = fmaxf(fmaf(acc[mf][nf][1], s1, b1), 0.0f);
            v1.x = fmaxf(fmaf(acc[mf][nf][2], s0, b0), 0.0f);
            v1.y = fmaxf(fmaf(acc[mf][nf][3], s1, b1), 0.0f);
            *(float2*)(out + obase + (size_t)rA * DOUT + d0) = v0;
            *(float2*)(out + obase + (size_t)rB * DOUT + d0) = v1;
        }
    }
}

// ---------------------------------------------------------------------------
extern "C" void kernel_launch(void* const* d_in, const int* in_sizes, int n_in,
                              void* d_out, int out_size) {
    const float* pre_x  = (const float*)d_in[0];
    const float* cur_x  = (const float*)d_in[1];
    const int*   up_idx = (const int*)d_in[2];
    const float* w      = (const float*)d_in[3];
    const float* bias   = (const float*)d_in[4];
    const float* gamma  = (const float*)d_in[5];
    const float* beta   = (const float*)d_in[6];
    const float* rmean  = (const float*)d_in[7];
    const float* rvar   = (const float*)d_in[8];
    float*       out    = (float*)d_out;

    dim3 tg(N_ / 32, CCUR / 32, B_);
    transpose_kernel<<<tg, dim3(32, 8)>>>(cur_x);
    wsplit_kernel<<<48, 256>>>(w);

    cudaFuncSetAttribute(fused_kernel, cudaFuncAttributeMaxDynamicSharedMemorySize, SM_TOT);
    dim3 grid(M_ / MT, B_);
    fused_kernel<<<grid, THREADS, SM_TOT>>>(pre_x, up_idx, bias, gamma,
                                            beta, rmean, rvar, out);
}

// round 8
// speedup vs baseline: 3.3141x; 1.6989x over previous
#include <cuda_runtime.h>
#include <cuda_bf16.h>
#include <cstdint>

// Problem constants
constexpr int B_   = 4;
constexpr int M_   = 65536;
constexpr int N_   = 16384;
constexpr int CPRE = 64;
constexpr int CCUR = 128;
constexpr int CIN  = 192;
constexpr int DOUT = 128;

constexpr int MT      = 128;
constexpr int THREADS = 512;   // 16 warps -> 4 per SMSP

// SMEM layouts (bf16 element strides; word stride ≡ 4 mod 8 -> conflict-free LDSM;
// all row starts 16B-aligned for cp.async)
constexpr int SXA = 136;   // pre_x tile, k-major: [64 k][128 m + pad]
constexpr int SXG = 136;   // gather tile, m-major: [128 m][128 k' + pad]
constexpr int SW  = 200;   // w tile, d-major: [128 d][192 k + pad]

constexpr int SM_IDX = 0;                       // 128 int
constexpr int SM_SC  = 512;                     // 128 f
constexpr int SM_BI  = 1024;                    // 128 f
constexpr int SM_XAH = 2048;
constexpr int SM_XAL = SM_XAH + 64 * SXA * 2;
constexpr int SM_XGH = SM_XAL + 64 * SXA * 2;
constexpr int SM_XGL = SM_XGH + 128 * SXG * 2;
constexpr int SM_WH  = SM_XGL + 128 * SXG * 2;
constexpr int SM_WL  = SM_WH + 128 * SW * 2;
constexpr int SM_TOT = SM_WL + 128 * SW * 2;    // 208896 (~204 KB)

// Pre-split scratch (bf16 hi/lo everywhere; converted ONCE in pre-passes)
__device__ uint16_t g_curT_h[(size_t)B_ * N_ * CCUR];   // (B,N,C) 16 MiB
__device__ uint16_t g_curT_l[(size_t)B_ * N_ * CCUR];
__device__ uint16_t g_pre_h[(size_t)B_ * CPRE * M_];    // (B,C,M) 32 MiB
__device__ uint16_t g_pre_l[(size_t)B_ * CPRE * M_];
__device__ uint32_t g_wh[128 * (SW / 2)];               // W hi smem image [d][k/2]
__device__ uint32_t g_wl[128 * (SW / 2)];

// ---------------------------------------------------------------------------
__device__ __forceinline__ uint32_t pk2(float a, float b) {
    __nv_bfloat162 t = __floats2bfloat162_rn(a, b);
    return *(uint32_t*)&t;
}
__device__ __forceinline__ void split2(float a, float b, uint32_t& hi, uint32_t& lo) {
    float ah = __bfloat162float(__float2bfloat16_rn(a));
    float bh = __bfloat162float(__float2bfloat16_rn(b));
    hi = pk2(ah, bh);
    lo = pk2(a - ah, b - bh);
}
__device__ __forceinline__ void split1(float a, uint16_t& hi, uint16_t& lo) {
    __nv_bfloat16 h = __float2bfloat16_rn(a);
    hi = *(uint16_t*)&h;
    __nv_bfloat16 l = __float2bfloat16_rn(a - __bfloat162float(h));
    lo = *(uint16_t*)&l;
}

// Transpose + split cur_x (B,C,N) -> (B,N,C) bf16 hi/lo
__global__ void transpose_split_kernel(const float* __restrict__ cur) {
    __shared__ float t[32][33];
    int b  = blockIdx.z;
    int c0 = blockIdx.y * 32;
    int n0 = blockIdx.x * 32;
    const float* src = cur + (size_t)b * CCUR * N_;
    #pragma unroll
    for (int r = threadIdx.y; r < 32; r += 8)
        t[r][threadIdx.x] = src[(size_t)(c0 + r) * N_ + n0 + threadIdx.x];
    __syncthreads();
    size_t dbase = (size_t)b * N_ * CCUR;
    #pragma unroll
    for (int r = threadIdx.y; r < 32; r += 8) {
        float v = t[threadIdx.x][r];
        uint16_t hi, lo;
        split1(v, hi, lo);
        size_t o = dbase + (size_t)(n0 + r) * CCUR + c0 + threadIdx.x;
        g_curT_h[o] = hi;
        g_curT_l[o] = lo;
    }
}

// Elementwise split pre_x (B,C,M) -> bf16 hi/lo, same layout (pair-packed stores)
__global__ void presplit_kernel(const float* __restrict__ pre) {
    size_t i = (size_t)blockIdx.x * blockDim.x + threadIdx.x;   // pair index
    if (i >= (size_t)B_ * CPRE * M_ / 2) return;
    float2 v = ((const float2*)pre)[i];
    uint32_t hi, lo;
    split2(v.x, v.y, hi, lo);
    ((uint32_t*)g_pre_h)[i] = hi;
    ((uint32_t*)g_pre_l)[i] = lo;
}

// Pre-split W into its smem image: [d][k] rows, hi/lo bf16 pairs
__global__ void wsplit_kernel(const float* __restrict__ w) {
    int i = blockIdx.x * 256 + threadIdx.x;   // 128 d x 96 k-pairs
    if (i >= DOUT * (CIN / 2)) return;
    int d = i & 127, kp = i >> 7;
    float a = w[(size_t)(2 * kp) * DOUT + d];
    float c = w[(size_t)(2 * kp + 1) * DOUT + d];
    uint32_t hi, lo;
    split2(a, c, hi, lo);
    g_wh[d * (SW / 2) + kp] = hi;
    g_wl[d * (SW / 2) + kp] = lo;
}

// ---------------------------------------------------------------------------
__device__ __forceinline__ uint32_t smem_u32(const void* p) {
    uint32_t a;
    asm("{ .reg .u64 t; cvta.to.shared.u64 t, %1; cvt.u32.u64 %0, t; }" : "=r"(a) : "l"(p));
    return a;
}
__device__ __forceinline__ void cp_async16(uint32_t dst, const void* src) {
    asm volatile("cp.async.cg.shared.global [%0], [%1], 16;" :: "r"(dst), "l"(src));
}

#define LDSM4(r0, r1, r2, r3, addr)                                          \
    asm volatile("ldmatrix.sync.aligned.m8n8.x4.shared.b16 {%0,%1,%2,%3}, [%4];" \
                 : "=r"(r0), "=r"(r1), "=r"(r2), "=r"(r3) : "r"(addr))
#define LDSM4T(r0, r1, r2, r3, addr)                                         \
    asm volatile("ldmatrix.sync.aligned.m8n8.x4.trans.shared.b16 {%0,%1,%2,%3}, [%4];" \
                 : "=r"(r0), "=r"(r1), "=r"(r2), "=r"(r3) : "r"(addr))
#define MMA16816(c, a, b)                                                    \
    asm volatile("mma.sync.aligned.m16n8k16.row.col.f32.bf16.bf16.f32 "       \
                 "{%0,%1,%2,%3}, {%4,%5,%6,%7}, {%8,%9}, {%0,%1,%2,%3};"      \
                 : "+f"((c)[0]), "+f"((c)[1]), "+f"((c)[2]), "+f"((c)[3])     \
                 : "r"((a)[0]), "r"((a)[1]), "r"((a)[2]), "r"((a)[3]),        \
                   "r"((b)[0]), "r"((b)[1]))

extern __shared__ char smc[];

__global__ __launch_bounds__(THREADS, 1)
void fused_kernel(const int* __restrict__ up_idx,
                  const float* __restrict__ bias,
                  const float* __restrict__ gamma,
                  const float* __restrict__ beta,
                  const float* __restrict__ rmean,
                  const float* __restrict__ rvar,
                  float* __restrict__ out) {
    const int b    = blockIdx.y;
    const int m0   = blockIdx.x * MT;
    const int tid  = threadIdx.x;
    const int wid  = tid >> 5;
    const int lane = tid & 31;

    int*   idx_s = (int*)(smc + SM_IDX);
    float* sc_s  = (float*)(smc + SM_SC);
    float* bi_s  = (float*)(smc + SM_BI);
    const uint32_t base_u32 = smem_u32(smc);

    if (tid < MT) {
        idx_s[tid] = up_idx[(size_t)b * M_ + m0 + tid] & (N_ - 1);
        float s = gamma[tid] * rsqrtf(rvar[tid] + 1e-5f);
        sc_s[tid] = s;
        bi_s[tid] = (bias[tid] - rmean[tid]) * s + beta[tid];
    }

    // ---- W tiles: pure cp.async of precomputed smem image ----
    {
        const char* sh = (const char*)g_wh;
        const char* sl = (const char*)g_wl;
        for (int i = tid; i < 128 * SW * 2 / 16; i += THREADS) {
            cp_async16(base_u32 + SM_WH + 16 * i, sh + 16 * i);
            cp_async16(base_u32 + SM_WL + 16 * i, sl + 16 * i);
        }
    }

    // ---- XA (pre_x, k-major): 64 rows x 256B, pure cp.async ----
    {
        const char* sh = (const char*)(g_pre_h + (size_t)b * CPRE * M_ + m0);
        const char* sl = (const char*)(g_pre_l + (size_t)b * CPRE * M_ + m0);
        for (int i = tid; i < 64 * 16; i += THREADS) {
            int k = i >> 4, c = i & 15;
            uint32_t doff = (uint32_t)(k * SXA * 2 + c * 16);
            size_t   soff = (size_t)k * M_ * 2 + c * 16;
            cp_async16(base_u32 + SM_XAH + doff, sh + soff);
            cp_async16(base_u32 + SM_XAL + doff, sl + soff);
        }
    }
    __syncthreads();   // idx_s visible

    // ---- XG (gather, m-major): 128 random rows x 256B, pure cp.async ----
    {
        const char* sh = (const char*)(g_curT_h + (size_t)b * N_ * CCUR);
        const char* sl = (const char*)(g_curT_l + (size_t)b * N_ * CCUR);
        for (int i = tid; i < 128 * 16; i += THREADS) {
            int m = i >> 4, c = i & 15;
            uint32_t doff = (uint32_t)(m * SXG * 2 + c * 16);
            size_t   soff = (size_t)idx_s[m] * CCUR * 2 + c * 16;
            cp_async16(base_u32 + SM_XGH + doff, sh + soff);
            cp_async16(base_u32 + SM_XGL + doff, sl + soff);
        }
    }
    asm volatile("cp.async.commit_group;");
    asm volatile("cp.async.wait_group 0;" ::: "memory");
    __syncthreads();

    // ---- mainloop: warp tile 32m x 32d ----
    const int wm = wid & 3;    // m-quarter (32)
    const int wd = wid >> 2;   // d-quarter (32)
    const int r  = lane & 7;
    const int q  = lane >> 3;

    // pre tile (trans): rows k, cols m
    const int krA = r + ((q >= 2) ? 8 : 0);
    const int mcA = wm * 32 + ((q & 1) ? 8 : 0);
    uint32_t aP_h = base_u32 + SM_XAH + (krA * SXA + mcA) * 2;
    uint32_t aP_l = base_u32 + SM_XAL + (krA * SXA + mcA) * 2;
    // gather tile (non-trans): rows m, cols k'
    const int mrA = wm * 32 + r + ((q & 1) ? 8 : 0);
    const int kcA = (q >= 2) ? 8 : 0;
    uint32_t aG_h = base_u32 + SM_XGH + (mrA * SXG + kcA) * 2;
    uint32_t aG_l = base_u32 + SM_XGL + (mrA * SXG + kcA) * 2;
    // w tile (non-trans): rows d, cols k
    const int drB = wd * 32 + r + ((q >= 2) ? 8 : 0);
    const int kcB = (q & 1) ? 8 : 0;
    uint32_t bW_h = base_u32 + SM_WH + (drB * SW + kcB) * 2;
    uint32_t bW_l = base_u32 + SM_WL + (drB * SW + kcB) * 2;

    float acc[2][4][4];
    #pragma unroll
    for (int i = 0; i < 2; i++)
        #pragma unroll
        for (int j = 0; j < 4; j++)
            #pragma unroll
            for (int e = 0; e < 4; e++) acc[i][j][e] = 0.0f;

    uint32_t ah[2][4], al[2][4], bh[4][2], bl[4][2];

    // ksteps 0..3: pre_x region (k-major, trans LDSM)
    #pragma unroll
    for (int ks = 0; ks < 4; ks++) {
        const int k0 = ks * 16;
        #pragma unroll
        for (int mf = 0; mf < 2; mf++) {
            uint32_t o = (uint32_t)(k0 * SXA + mf * 16) * 2;
            LDSM4T(ah[mf][0], ah[mf][1], ah[mf][2], ah[mf][3], aP_h + o);
            LDSM4T(al[mf][0], al[mf][1], al[mf][2], al[mf][3], aP_l + o);
        }
        #pragma unroll
        for (int g = 0; g < 2; g++) {
            uint32_t o = (uint32_t)(g * 16 * SW + k0) * 2;
            LDSM4(bh[2*g][0], bh[2*g][1], bh[2*g+1][0], bh[2*g+1][1], bW_h + o);
            LDSM4(bl[2*g][0], bl[2*g][1], bl[2*g+1][0], bl[2*g+1][1], bW_l + o);
        }
        #pragma unroll
        for (int mf = 0; mf < 2; mf++)
            #pragma unroll
            for (int nf = 0; nf < 4; nf++) MMA16816(acc[mf][nf], ah[mf], bh[nf]);
        #pragma unroll
        for (int mf = 0; mf < 2; mf++)
            #pragma unroll
            for (int nf = 0; nf < 4; nf++) MMA16816(acc[mf][nf], ah[mf], bl[nf]);
        #pragma unroll
        for (int mf = 0; mf < 2; mf++)
            #pragma unroll
            for (int nf = 0; nf < 4; nf++) MMA16816(acc[mf][nf], al[mf], bh[nf]);
    }

    // ksteps 4..11: gather region (m-major, non-trans LDSM)
    #pragma unroll
    for (int ks = 4; ks < 12; ks++) {
        const int k0  = ks * 16;
        const int kp0 = k0 - 64;
        #pragma unroll
        for (int mf = 0; mf < 2; mf++) {
            uint32_t o = (uint32_t)(mf * 16 * SXG + kp0) * 2;
            LDSM4(ah[mf][0], ah[mf][1], ah[mf][2], ah[mf][3], aG_h + o);
            LDSM4(al[mf][0], al[mf][1], al[mf][2], al[mf][3], aG_l + o);
        }
        #pragma unroll
        for (int g = 0; g < 2; g++) {
            uint32_t o = (uint32_t)(g * 16 * SW + k0) * 2;
            LDSM4(bh[2*g][0], bh[2*g][1], bh[2*g+1][0], bh[2*g+1][1], bW_h + o);
            LDSM4(bl[2*g][0], bl[2*g][1], bl[2*g+1][0], bl[2*g+1][1], bW_l + o);
        }
        #pragma unroll
        for (int mf = 0; mf < 2; mf++)
            #pragma unroll
            for (int nf = 0; nf < 4; nf++) MMA16816(acc[mf][nf], ah[mf], bh[nf]);
        #pragma unroll
        for (int mf = 0; mf < 2; mf++)
            #pragma unroll
            for (int nf = 0; nf < 4; nf++) MMA16816(acc[mf][nf], ah[mf], bl[nf]);
        #pragma unroll
        for (int mf = 0; mf < 2; mf++)
            #pragma unroll
            for (int nf = 0; nf < 4; nf++) MMA16816(acc[mf][nf], al[mf], bh[nf]);
    }

    // ---- epilogue: BN + ReLU + STG.64 ----
    const int gid = lane >> 2;
    const int tig = lane & 3;
    const size_t obase = ((size_t)b * M_ + m0) * DOUT;

    #pragma unroll
    for (int nf = 0; nf < 4; nf++) {
        int d0 = wd * 32 + nf * 8 + 2 * tig;
        float s0 = sc_s[d0], s1 = sc_s[d0 + 1];
        float b0 = bi_s[d0], b1 = bi_s[d0 + 1];
        #pragma unroll
        for (int mf = 0; mf < 2; mf++) {
            int rA = wm * 32 + mf * 16 + gid;
            int rB = rA + 8;
            float2 v0, v1;
            v0.x = fmaxf(fmaf(acc[mf][nf][0], s0, b0), 0.0f);
            v0.y = fmaxf(fmaf(acc[mf][nf][1], s1, b1), 0.0f);
            v1.x = fmaxf(fmaf(acc[mf][nf][2], s0, b0), 0.0f);
            v1.y = fmaxf(fmaf(acc[mf][nf][3], s1, b1), 0.0f);
            *(float2*)(out + obase + (size_t)rA * DOUT + d0) = v0;
            *(float2*)(out + obase + (size_t)rB * DOUT + d0) = v1;
        }
    }
}

// ---------------------------------------------------------------------------
extern "C" void kernel_launch(void* const* d_in, const int* in_sizes, int n_in,
                              void* d_out, int out_size) {
    const float* pre_x  = (const float*)d_in[0];
    const float* cur_x  = (const float*)d_in[1];
    const int*   up_idx = (const int*)d_in[2];
    const float* w      = (const float*)d_in[3];
    const float* bias   = (const float*)d_in[4];
    const float* gamma  = (const float*)d_in[5];
    const float* beta   = (const float*)d_in[6];
    const float* rmean  = (const float*)d_in[7];
    const float* rvar   = (const float*)d_in[8];
    float*       out    = (float*)d_out;

    dim3 tg(N_ / 32, CCUR / 32, B_);
    transpose_split_kernel<<<tg, dim3(32, 8)>>>(cur_x);
    presplit_kernel<<<(int)(((size_t)B_ * CPRE * M_ / 2 + 255) / 256), 256>>>(pre_x);
    wsplit_kernel<<<48, 256>>>(w);

    cudaFuncSetAttribute(fused_kernel, cudaFuncAttributeMaxDynamicSharedMemorySize, SM_TOT);
    dim3 grid(M_ / MT, B_);
    fused_kernel<<<grid, THREADS, SM_TOT>>>(up_idx, bias, gamma, beta,
                                            rmean, rvar, out);
}